// round 1
// baseline (speedup 1.0000x reference)
#include <cuda_runtime.h>
#include <cstdint>

#define NPTS 4096
#define DDIM 64

// ---------------- device scratch (no allocations allowed) ----------------
__device__ float g_sqnorm[NPTS];      // per-row squared norms
__device__ float g_partial_sq[16];    // per-block partial sums of sq norms
__device__ float g_colsum[DDIM];      // column sums of X
__device__ float g_c;                 // log2(e) / (4*bw)

// ---------------- kernel 1: row squared norms + partial total ----------------
__global__ void rownorm_kernel(const float* __restrict__ X) {
    int r = blockIdx.x * 256 + threadIdx.x;   // 16 blocks x 256 = 4096 rows
    const float4* p = (const float4*)(X + (size_t)r * DDIM);
    float s = 0.f;
#pragma unroll
    for (int i = 0; i < 16; i++) {
        float4 v = p[i];
        s += v.x * v.x + v.y * v.y + v.z * v.z + v.w * v.w;
    }
    g_sqnorm[r] = s;

    // block reduce s
    __shared__ float red[256];
    red[threadIdx.x] = s;
    __syncthreads();
#pragma unroll
    for (int off = 128; off > 0; off >>= 1) {
        if (threadIdx.x < off) red[threadIdx.x] += red[threadIdx.x + off];
        __syncthreads();
    }
    if (threadIdx.x == 0) g_partial_sq[blockIdx.x] = red[0];
}

// ---------------- kernel 2: column sums (for ||sum_i x_i||^2) ----------------
__global__ void colsum_kernel(const float* __restrict__ X) {
    int c = blockIdx.x;   // 64 blocks, one per column
    float s = 0.f;
    for (int r = threadIdx.x; r < NPTS; r += 256)
        s += X[(size_t)r * DDIM + c];
    __shared__ float red[256];
    red[threadIdx.x] = s;
    __syncthreads();
#pragma unroll
    for (int off = 128; off > 0; off >>= 1) {
        if (threadIdx.x < off) red[threadIdx.x] += red[threadIdx.x + off];
        __syncthreads();
    }
    if (threadIdx.x == 0) g_colsum[c] = red[0];
}

// ---------------- kernel 3: bandwidth -> exp2 coefficient ----------------
__global__ void finalize_kernel() {
    if (threadIdx.x == 0) {
        float ss = 0.f;
#pragma unroll
        for (int i = 0; i < 16; i++) ss += g_partial_sq[i];
        float cs = 0.f;
#pragma unroll
        for (int c = 0; c < DDIM; c++) { float v = g_colsum[c]; cs += v * v; }
        // sum(L2) = 2*N*sum(||xi||^2) - 2*||sum xi||^2  (clamp effect negligible)
        float bwsum = 2.f * (float)NPTS * ss - 2.f * cs;
        float bw = bwsum / ((float)NPTS * (float)(NPTS - 1));
        // t = exp(-L2/(4bw)) = 2^(-L2 * log2(e)/(4bw))
        g_c = 1.4426950408889634f / (4.f * bw);
    }
}

// ---------------- kernel 4: fused Gram + RBF-sum epilogue ----------------
// 128x128 tile per block, 256 threads, 8x8 outputs per thread, K in 2 chunks of 32.
__global__ __launch_bounds__(256, 2)
void rbf_main_kernel(const float* __restrict__ X, float* __restrict__ out) {
    __shared__ float As[32][128];   // k-major
    __shared__ float Bs[32][128];
    __shared__ float sqa[128];
    __shared__ float sqb[128];

    const int tid = threadIdx.x;
    const int tx = tid & 15;          // 0..15 -> col group
    const int ty = tid >> 4;          // 0..15 -> row group
    const int rowBase = blockIdx.y * 128;
    const int colBase = blockIdx.x * 128;

    if (tid < 128) sqa[tid] = g_sqnorm[rowBase + tid];
    else           sqb[tid - 128] = g_sqnorm[colBase + tid - 128];

    float acc[8][8];
#pragma unroll
    for (int i = 0; i < 8; i++)
#pragma unroll
        for (int j = 0; j < 8; j++) acc[i][j] = 0.f;

#pragma unroll
    for (int kc = 0; kc < 2; kc++) {
        __syncthreads();
        // Load 128 rows x 32 cols of each operand tile; float4 along k, store k-major.
#pragma unroll
        for (int i = 0; i < 4; i++) {
            int idx = tid + i * 256;          // 0..1023
            int r = idx >> 3;                 // 0..127
            int f = idx & 7;                  // float4 index within 32-col chunk
            float4 va = *(const float4*)(X + (size_t)(rowBase + r) * DDIM + kc * 32 + f * 4);
            As[f * 4 + 0][r] = va.x;
            As[f * 4 + 1][r] = va.y;
            As[f * 4 + 2][r] = va.z;
            As[f * 4 + 3][r] = va.w;
            float4 vb = *(const float4*)(X + (size_t)(colBase + r) * DDIM + kc * 32 + f * 4);
            Bs[f * 4 + 0][r] = vb.x;
            Bs[f * 4 + 1][r] = vb.y;
            Bs[f * 4 + 2][r] = vb.z;
            Bs[f * 4 + 3][r] = vb.w;
        }
        __syncthreads();

#pragma unroll
        for (int k = 0; k < 32; k++) {
            float a[8], b[8];
            *(float4*)&a[0] = *(const float4*)&As[k][ty * 8];
            *(float4*)&a[4] = *(const float4*)&As[k][ty * 8 + 4];
            *(float4*)&b[0] = *(const float4*)&Bs[k][tx * 8];
            *(float4*)&b[4] = *(const float4*)&Bs[k][tx * 8 + 4];
#pragma unroll
            for (int i = 0; i < 8; i++)
#pragma unroll
                for (int j = 0; j < 8; j++)
                    acc[i][j] = fmaf(a[i], b[j], acc[i][j]);
        }
    }

    // Epilogue: L2 -> t = 2^(-L2*c); out = t + t^2 + t^4 + t^8 + t^16
    const float c = g_c;
#pragma unroll
    for (int i = 0; i < 8; i++) {
        float sa = sqa[ty * 8 + i];
        float res[8];
#pragma unroll
        for (int j = 0; j < 8; j++) {
            float l2 = fmaxf(sa + sqb[tx * 8 + j] - 2.f * acc[i][j], 0.f);
            float t;
            asm("ex2.approx.ftz.f32 %0, %1;" : "=f"(t) : "f"(-l2 * c));
            float t2 = t * t;
            float t4 = t2 * t2;
            float t8 = t4 * t4;
            float t16 = t8 * t8;
            res[j] = t + t2 + t4 + t8 + t16;
        }
        float* orow = out + (size_t)(rowBase + ty * 8 + i) * NPTS + colBase + tx * 8;
        *(float4*)(orow)     = *(float4*)&res[0];
        *(float4*)(orow + 4) = *(float4*)&res[4];
    }
}

// ---------------- launch ----------------
extern "C" void kernel_launch(void* const* d_in, const int* in_sizes, int n_in,
                              void* d_out, int out_size) {
    const float* X = (const float*)d_in[0];
    float* out = (float*)d_out;

    rownorm_kernel<<<16, 256>>>(X);
    colsum_kernel<<<64, 256>>>(X);
    finalize_kernel<<<1, 32>>>();
    dim3 grid(NPTS / 128, NPTS / 128);
    rbf_main_kernel<<<grid, 256>>>(X, out);
}